// round 13
// baseline (speedup 1.0000x reference)
#include <cuda_runtime.h>
#include <cuda_bf16.h>

// Problem dims  (V, E, H, N, L = 32000, 512, 1024, 16, 128)
#define VV 32000
#define NB 16
#define LL 128
#define EE 512
#define HH 1024
#define G4 4096
#define MM (NB*LL)
#define RB 128           // persistent recurrence CTAs (1/SM, co-resident)
#define NGRP 8
#define GSZ  16

// Scratch
__device__ __align__(16) float g_X0[(size_t)MM * G4];
__device__ __align__(16) float g_X1[(size_t)MM * G4];
__device__ __align__(16) float g_H0[(size_t)MM * HH];
// h carried between steps as bf16 hi/lo, [b][k] rows (transposed for B-frags)
__device__ __align__(16) __nv_bfloat16 g_hT_hi[2][NB * HH];
__device__ __align__(16) __nv_bfloat16 g_hT_lo[2][NB * HH];
// Monotonic barrier state: NEVER reset; all values derived from atomic returns.
__device__ __align__(16) unsigned g_grpm[NGRP * 64];   // group counters, 256B apart
__device__ unsigned g_rootm = 0;
__device__ unsigned g_genm  = 0;

__device__ __forceinline__ float sigf(float x) { return 1.0f / (1.0f + __expf(-x)); }

__device__ __forceinline__ void stcg_b16(__nv_bfloat16* p, __nv_bfloat16 v) {
    unsigned short u = *(unsigned short*)&v;
    asm volatile("st.global.cg.u16 [%0], %1;" :: "l"(p), "h"(u) : "memory");
}

// ---- grid barrier: monotonic two-level tree, NO resets --------------------
__device__ __forceinline__ void grid_sync() {
    __threadfence();
    __syncthreads();
    if (threadIdx.x == 0) {
        const int g = blockIdx.x >> 4;
        unsigned old = atomicAdd(&g_grpm[g * 64], 1u);
        unsigned n = old >> 4;                  // barrier instance
        bool released = false;
        if ((old & 15u) == 15u) {
            __threadfence();
            unsigned ro = atomicAdd(&g_rootm, 1u);
            if ((ro & 7u) == 7u) {
                __threadfence();
                atomicAdd(&g_genm, 1u);         // release: gen -> n+1
                released = true;
            }
        }
        if (!released) {
            while ((int)(((volatile unsigned*)&g_genm)[0] - (n + 1u)) < 0) { }
        }
        __threadfence();
    }
    __syncthreads();
}

// ---- bf16 hi/lo split pack ------------------------------------------------
__device__ __forceinline__ void cvt_pair(float x0, float x1, unsigned& hi, unsigned& lo) {
    __nv_bfloat16 h0 = __float2bfloat16(x0);
    __nv_bfloat16 h1 = __float2bfloat16(x1);
    float r0 = x0 - __bfloat162float(h0);
    float r1 = x1 - __bfloat162float(h1);
    __nv_bfloat162 hp = __halves2bfloat162(h0, h1);
    __nv_bfloat162 lp = __halves2bfloat162(__float2bfloat16(r0), __float2bfloat16(r1));
    hi = *(unsigned*)&hp;
    lo = *(unsigned*)&lp;
}

#define MMA4(d, a, b0r, b1r) \
    asm volatile("mma.sync.aligned.m16n8k16.row.col.f32.bf16.bf16.f32 " \
        "{%0,%1,%2,%3}, {%4,%5,%6,%7}, {%8,%9}, {%0,%1,%2,%3};" \
        : "+f"((d)[0]), "+f"((d)[1]), "+f"((d)[2]), "+f"((d)[3]) \
        : "r"((a)[0]), "r"((a)[1]), "r"((a)[2]), "r"((a)[3]), "r"(b0r), "r"(b1r))

// ---------------------------------------------------------------------------
// Tensor-core GEMM (unchanged from R12 — passed, rel_err 6.4e-6)
// ---------------------------------------------------------------------------
template <int K>
__global__ __launch_bounds__(256) void gemm_tc(
    const float* __restrict__ Aext,
    const int*   __restrict__ tokens,
    const float* __restrict__ Bw,
    const float* __restrict__ bias,
    int a_sel, int c_sel)
{
    __shared__ __align__(16) unsigned sAhi[128 * 9];
    __shared__ __align__(16) unsigned sAlo[128 * 9];
    __shared__ __align__(16) unsigned sBhi[128 * 9];
    __shared__ __align__(16) unsigned sBlo[128 * 9];

    float* C = c_sel ? g_X1 : g_X0;
    const int bm = blockIdx.y, br = blockIdx.x;
    const int tid = threadIdx.x, lane = tid & 31, wid = tid >> 5;

    const int ra = tid >> 1;
    const int kc = (tid & 1) * 8;

    const float* arow;
    if (tokens) {
        int gm = bm * 128 + ra;
        int tok = tokens[(gm & (NB - 1)) * LL + (gm >> 4)];
        tok = min(max(tok, 0), VV - 1);
        arow = Aext + (size_t)tok * K + kc;
    } else {
        const float* A = a_sel ? g_H0 : Aext;
        arow = A + (size_t)(bm * 128 + ra) * K + kc;
    }
    const float* brow = Bw + (size_t)(br * 128 + ra) * K + kc;

    const int wm = (wid & 3) * 32;
    const int wn = (wid >> 2) * 64;
    const int gid = lane >> 2, qc = lane & 3;

    float acc[2][8][4];
#pragma unroll
    for (int mi = 0; mi < 2; mi++)
#pragma unroll
        for (int j = 0; j < 8; j++)
#pragma unroll
            for (int e = 0; e < 4; e++) acc[mi][j][e] = 0.0f;

#define STCVT(dsthi, dstlo, v0, v1)  do {                                   \
        unsigned h_, l_;                                                    \
        cvt_pair((v0).x, (v0).y, h_, l_); dsthi[ra*9 + kc/2 + 0] = h_; dstlo[ra*9 + kc/2 + 0] = l_; \
        cvt_pair((v0).z, (v0).w, h_, l_); dsthi[ra*9 + kc/2 + 1] = h_; dstlo[ra*9 + kc/2 + 1] = l_; \
        cvt_pair((v1).x, (v1).y, h_, l_); dsthi[ra*9 + kc/2 + 2] = h_; dstlo[ra*9 + kc/2 + 2] = l_; \
        cvt_pair((v1).z, (v1).w, h_, l_); dsthi[ra*9 + kc/2 + 3] = h_; dstlo[ra*9 + kc/2 + 3] = l_; \
    } while (0)

    {
        float4 av0 = *(const float4*)(arow);
        float4 av1 = *(const float4*)(arow + 4);
        float4 bv0 = *(const float4*)(brow);
        float4 bv1 = *(const float4*)(brow + 4);
        STCVT(sAhi, sAlo, av0, av1);
        STCVT(sBhi, sBlo, bv0, bv1);
    }
    __syncthreads();

#pragma unroll 1
    for (int k0 = 0; k0 < K; k0 += 16) {
        const bool more = (k0 + 16) < K;
        float4 nav0, nav1, nbv0, nbv1;
        if (more) {
            nav0 = *(const float4*)(arow + k0 + 16);
            nav1 = *(const float4*)(arow + k0 + 20);
            nbv0 = *(const float4*)(brow + k0 + 16);
            nbv1 = *(const float4*)(brow + k0 + 20);
        }

        unsigned ahi[2][4], alo[2][4];
#pragma unroll
        for (int mi = 0; mi < 2; mi++) {
            int r0 = (wm + mi * 16 + gid) * 9;
            int r8 = r0 + 8 * 9;
            ahi[mi][0] = sAhi[r0 + qc];     ahi[mi][1] = sAhi[r8 + qc];
            ahi[mi][2] = sAhi[r0 + qc + 4]; ahi[mi][3] = sAhi[r8 + qc + 4];
            alo[mi][0] = sAlo[r0 + qc];     alo[mi][1] = sAlo[r8 + qc];
            alo[mi][2] = sAlo[r0 + qc + 4]; alo[mi][3] = sAlo[r8 + qc + 4];
        }

#pragma unroll
        for (int j = 0; j < 8; j++) {
            int rb = (wn + j * 8 + gid) * 9;
            unsigned bh0 = sBhi[rb + qc], bh1 = sBhi[rb + qc + 4];
            unsigned bl0 = sBlo[rb + qc], bl1 = sBlo[rb + qc + 4];
#pragma unroll
            for (int mi = 0; mi < 2; mi++) {
                MMA4(acc[mi][j], ahi[mi], bh0, bh1);
                MMA4(acc[mi][j], ahi[mi], bl0, bl1);
                MMA4(acc[mi][j], alo[mi], bh0, bh1);
            }
        }

        if (more) {
            __syncthreads();
            STCVT(sAhi, sAlo, nav0, nav1);
            STCVT(sBhi, sBlo, nbv0, nbv1);
            __syncthreads();
        }
    }
#undef STCVT

#pragma unroll
    for (int j = 0; j < 8; j++) {
        int gc = br * 128 + wn + j * 8 + qc * 2;
        float b0v = bias[gc], b1v = bias[gc + 1];
#pragma unroll
        for (int mi = 0; mi < 2; mi++) {
            int gm0 = bm * 128 + wm + mi * 16 + gid;
            float2 o0 = make_float2(acc[mi][j][0] + b0v, acc[mi][j][1] + b1v);
            float2 o1 = make_float2(acc[mi][j][2] + b0v, acc[mi][j][3] + b1v);
            *(float2*)(C + (size_t)gm0 * G4 + gc)       = o0;
            *(float2*)(C + (size_t)(gm0 + 8) * G4 + gc) = o1;
        }
    }
}

// ---------------------------------------------------------------------------
// Persistent TENSOR-CORE LSTM recurrence. 128 CTAs x 256 thr.
// Per CTA-step: gates[32 m=(g*8+jw)][16 b] = W[32][1024] x h[1024][16].
// Warp w: m-tile mt=w&1, k-quarter kr=w>>1 (16 k-tiles of 16) -> 96 MMAs.
// Smem rows padded to 516 u32 (stride = 4 banks: frag LDS conflict-free).
// h flows between steps as bf16 hi/lo in g_hT (double-buffered, L2 via .cg).
// ---------------------------------------------------------------------------
__global__ __launch_bounds__(256) void lstm_rec(
    const float* __restrict__ Whh,
    float* __restrict__ Out,
    int xsel, int mode)
{
    extern __shared__ __align__(16) unsigned smu[];
    unsigned* sWhi = smu;                  // 32 rows x 516
    unsigned* sWlo = sWhi + 32 * 516;
    unsigned* sHhi = sWlo + 32 * 516;      // 16 rows x 516
    unsigned* sHlo = sHhi + 16 * 516;
    float* red = (float*)(sHlo + 16 * 516);  // 8 warps x 256
    float* gs  = red + 2048;               // 512
    float* xs  = gs + 512;                 // 512

    const float* Xg = xsel ? g_X1 : g_X0;
    const int tid = threadIdx.x, lane = tid & 31, wp = tid >> 5;
    const int gid = lane >> 2, qc = lane & 3;
    const int mt = wp & 1, kr = wp >> 1;

    // ---- preload + convert weight slice: rows m=g*8+jw, k 0..1023 ----
    for (int i = tid; i < 8192; i += 256) {
        int m = i >> 8, cc = i & 255;   // cc = float4 chunk in row
        const float4 wv = *(const float4*)(
            Whh + (size_t)((m >> 3) * HH + blockIdx.x * 8 + (m & 7)) * HH + cc * 4);
        unsigned h0, l0, h1, l1;
        cvt_pair(wv.x, wv.y, h0, l0);
        cvt_pair(wv.z, wv.w, h1, l1);
        int base = m * 516 + cc * 2;
        sWhi[base] = h0; sWhi[base + 1] = h1;
        sWlo[base] = l0; sWlo[base + 1] = l1;
    }
    // zero h rows (t=0 state); sHhi and sHlo are contiguous
    for (int i = tid; i < 2 * 16 * 516; i += 256) sHhi[i] = 0u;

    float creg = 0.0f;
    __syncthreads();

    for (int t = 0; t < LL; t++) {
        // X gate-slice prefetch (overlaps h staging)
        float2 xv;
        int xb = tid >> 4, xr = tid & 15, xg = xr >> 2, xj2 = (xr & 3) << 1;
        xv = *(const float2*)(Xg + (size_t)(t * NB + xb) * G4 + xg * HH + blockIdx.x * 8 + xj2);

        if (t > 0) {
            // stage h_t rows [b][k] (bf16) from L2 into padded smem
            int b = tid >> 4, c = tid & 15;
            const float4* ph = (const float4*)(g_hT_hi[t & 1]) + b * 128 + c * 8;
            const float4* pl = (const float4*)(g_hT_lo[t & 1]) + b * 128 + c * 8;
            float4* dh = (float4*)(sHhi + b * 516 + c * 32);
            float4* dl = (float4*)(sHlo + b * 516 + c * 32);
#pragma unroll
            for (int q = 0; q < 8; q++) dh[q] = __ldcg(ph + q);
#pragma unroll
            for (int q = 0; q < 8; q++) dl[q] = __ldcg(pl + q);
        }
        xs[xj2 * 64 + xg * 16 + xb]       = xv.x;
        xs[(xj2 + 1) * 64 + xg * 16 + xb] = xv.y;
        __syncthreads();

        // ---- tensor-core GEMV: warp (mt, kr), 16 k-tiles, 2 n-tiles ----
        float acc0[4] = {0.f, 0.f, 0.f, 0.f};
        float acc1[4] = {0.f, 0.f, 0.f, 0.f};
        {
            const int aRow0 = (mt * 16 + gid) * 516;
            const int aRow8 = aRow0 + 8 * 516;
            const int bRow0 = gid * 516;
            const int bRow1 = (8 + gid) * 516;
#pragma unroll
            for (int kt = 0; kt < 16; kt++) {
                const int kp = kr * 128 + kt * 8;
                unsigned ah[4], al[4];
                ah[0] = sWhi[aRow0 + kp + qc];
                ah[1] = sWhi[aRow8 + kp + qc];
                ah[2] = sWhi[aRow0 + kp + qc + 4];
                ah[3] = sWhi[aRow8 + kp + qc + 4];
                al[0] = sWlo[aRow0 + kp + qc];
                al[1] = sWlo[aRow8 + kp + qc];
                al[2] = sWlo[aRow0 + kp + qc + 4];
                al[3] = sWlo[aRow8 + kp + qc + 4];
                unsigned bh0 = sHhi[bRow0 + kp + qc], bh1 = sHhi[bRow0 + kp + qc + 4];
                unsigned bl0 = sHlo[bRow0 + kp + qc], bl1 = sHlo[bRow0 + kp + qc + 4];
                MMA4(acc0, ah, bh0, bh1);
                MMA4(acc0, ah, bl0, bl1);
                MMA4(acc0, al, bh0, bh1);
                bh0 = sHhi[bRow1 + kp + qc]; bh1 = sHhi[bRow1 + kp + qc + 4];
                bl0 = sHlo[bRow1 + kp + qc]; bl1 = sHlo[bRow1 + kp + qc + 4];
                MMA4(acc1, ah, bh0, bh1);
                MMA4(acc1, ah, bl0, bl1);
                MMA4(acc1, al, bh0, bh1);
            }
        }
        // write k-partial accumulators
        {
            float4* rw = (float4*)(red + wp * 256 + lane * 8);
            rw[0] = make_float4(acc0[0], acc0[1], acc0[2], acc0[3]);
            rw[1] = make_float4(acc1[0], acc1[1], acc1[2], acc1[3]);
        }
        __syncthreads();

        // ---- k-reduction (warps 0,1) + scatter gates to gs[jw][g][b] ----
        if (wp < 2) {
#pragma unroll
            for (int e = 0; e < 8; e++) {
                float s = red[(0 + wp) * 256 + lane * 8 + e]
                        + red[(2 + wp) * 256 + lane * 8 + e]
                        + red[(4 + wp) * 256 + lane * 8 + e]
                        + red[(6 + wp) * 256 + lane * 8 + e];
                int nt = e >> 2, ee = e & 3;
                int row = wp * 16 + gid + ((ee >> 1) ? 8 : 0);   // m = g*8+jw
                int b = nt * 8 + qc * 2 + (ee & 1);
                gs[(row & 7) * 64 + (row >> 3) * 16 + b] = s;
            }
        }
        __syncthreads();

        // ---- gate nonlinearity + state update (warp wp owns column jw=wp) --
        if (lane < 16) {
            const int b = lane;
            const int j = blockIdx.x * 8 + wp;
            float gi = gs[wp * 64 +  0 + b] + xs[wp * 64 +  0 + b];
            float gf = gs[wp * 64 + 16 + b] + xs[wp * 64 + 16 + b];
            float gg = gs[wp * 64 + 32 + b] + xs[wp * 64 + 32 + b];
            float go = gs[wp * 64 + 48 + b] + xs[wp * 64 + 48 + b];
            float c = sigf(gf) * creg + sigf(gi) * tanhf(gg);
            float h = sigf(go) * tanhf(c);
            creg = c;
            __nv_bfloat16 hh = __float2bfloat16(h);
            __nv_bfloat16 hl = __float2bfloat16(h - __bfloat162float(hh));
            stcg_b16(&g_hT_hi[(t + 1) & 1][b * HH + j], hh);
            stcg_b16(&g_hT_lo[(t + 1) & 1][b * HH + j], hl);
            if (mode == 0)
                g_H0[(size_t)(t * NB + b) * HH + j] = h;
            else
                Out[(size_t)b * (LL * HH) + (size_t)t * HH + j] = h;
        }

        if (t != LL - 1) grid_sync();
    }
}

// ---------------------------------------------------------------------------
extern "C" void kernel_launch(void* const* d_in, const int* in_sizes, int n_in,
                              void* d_out, int out_size)
{
    const int*   x    = nullptr;
    const float* emb  = nullptr;
    const float* wih0 = nullptr;
    const float* bias_[2] = {nullptr, nullptr};
    const float* w4[3] = {nullptr, nullptr, nullptr};
    int nbias = 0, nw = 0;
    for (int i = 0; i < n_in; i++) {
        long long sz = in_sizes[i];
        if (sz == (long long)NB * LL)             x = (const int*)d_in[i];
        else if (sz == (long long)VV * EE)        emb = (const float*)d_in[i];
        else if (sz == (long long)G4 * EE)        wih0 = (const float*)d_in[i];
        else if (sz == (long long)G4)             { if (nbias < 2) bias_[nbias++] = (const float*)d_in[i]; }
        else if (sz == (long long)G4 * HH)        { if (nw < 3) w4[nw++] = (const float*)d_in[i]; }
    }
    if (!x || !emb || !wih0 || nbias < 2 || nw < 3) {
        x = (const int*)d_in[0];
        emb = (const float*)d_in[1];
        wih0 = (const float*)d_in[2];
        w4[0] = (const float*)d_in[3];
        bias_[0] = (const float*)d_in[4];
        w4[1] = (const float*)d_in[5];
        w4[2] = (const float*)d_in[6];
        bias_[1] = (const float*)d_in[7];
    }
    const float* whh0 = w4[0];
    const float* b0   = bias_[0];
    const float* wih1 = w4[1];
    const float* whh1 = w4[2];
    const float* b1   = bias_[1];
    float* out = (float*)d_out;

    // smem: (32+32+16+16)*516 u32 + (2048+512+512) floats = 210432 B
    const int smem_rec = (96 * 516) * 4 + (2048 + 512 + 512) * 4;
    cudaFuncSetAttribute(lstm_rec, cudaFuncAttributeMaxDynamicSharedMemorySize, smem_rec);

    dim3 ggrid(G4 / 128, MM / 128);  // (32, 16)

    gemm_tc<EE><<<ggrid, 256>>>(emb, x, wih0, b0, 0, 0);
    lstm_rec<<<RB, 256, smem_rec>>>(whh0, out, 0, 0);
    gemm_tc<HH><<<ggrid, 256>>>(emb, nullptr, wih1, b1, 1, 1);
    lstm_rec<<<RB, 256, smem_rec>>>(whh1, out, 1, 1);
}

// round 14
// speedup vs baseline: 1.0049x; 1.0049x over previous
#include <cuda_runtime.h>
#include <cuda_bf16.h>

// Problem dims  (V, E, H, N, L = 32000, 512, 1024, 16, 128)
#define VV 32000
#define NB 16
#define LL 128
#define EE 512
#define HH 1024
#define G4 4096
#define MM (NB*LL)
#define RB 128           // persistent recurrence CTAs (1/SM, co-resident)
#define NGRP 8
#define GSZ  16

// Scratch
__device__ __align__(16) float g_X0[(size_t)MM * G4];
__device__ __align__(16) float g_X1[(size_t)MM * G4];
__device__ __align__(16) float g_H0[(size_t)MM * HH];
// h carried between steps as bf16 hi/lo, [b][k] rows (transposed for B-frags)
__device__ __align__(16) __nv_bfloat16 g_hT_hi[2][NB * HH];
__device__ __align__(16) __nv_bfloat16 g_hT_lo[2][NB * HH];
// Monotonic barrier state: NEVER reset; all values derived from atomic returns.
__device__ __align__(16) unsigned g_grpm[NGRP * 64];   // group counters, 256B apart
__device__ unsigned g_rootm = 0;
__device__ unsigned g_genm  = 0;

__device__ __forceinline__ float sigf(float x) { return 1.0f / (1.0f + __expf(-x)); }

__device__ __forceinline__ void stcg_b16(__nv_bfloat16* p, __nv_bfloat16 v) {
    unsigned short u = *(unsigned short*)&v;
    asm volatile("st.global.cg.u16 [%0], %1;" :: "l"(p), "h"(u) : "memory");
}

// ---- grid barrier: monotonic two-level tree, NO resets --------------------
__device__ __forceinline__ void grid_sync() {
    __threadfence();
    __syncthreads();
    if (threadIdx.x == 0) {
        const int g = blockIdx.x >> 4;
        unsigned old = atomicAdd(&g_grpm[g * 64], 1u);
        unsigned n = old >> 4;                  // barrier instance
        bool released = false;
        if ((old & 15u) == 15u) {
            __threadfence();
            unsigned ro = atomicAdd(&g_rootm, 1u);
            if ((ro & 7u) == 7u) {
                __threadfence();
                atomicAdd(&g_genm, 1u);         // release: gen -> n+1
                released = true;
            }
        }
        if (!released) {
            while ((int)(((volatile unsigned*)&g_genm)[0] - (n + 1u)) < 0) { }
        }
        __threadfence();
    }
    __syncthreads();
}

// ---- bf16 hi/lo split pack ------------------------------------------------
__device__ __forceinline__ void cvt_pair(float x0, float x1, unsigned& hi, unsigned& lo) {
    __nv_bfloat16 h0 = __float2bfloat16(x0);
    __nv_bfloat16 h1 = __float2bfloat16(x1);
    float r0 = x0 - __bfloat162float(h0);
    float r1 = x1 - __bfloat162float(h1);
    __nv_bfloat162 hp = __halves2bfloat162(h0, h1);
    __nv_bfloat162 lp = __halves2bfloat162(__float2bfloat16(r0), __float2bfloat16(r1));
    hi = *(unsigned*)&hp;
    lo = *(unsigned*)&lp;
}

#define MMA4(d, a, b0r, b1r) \
    asm volatile("mma.sync.aligned.m16n8k16.row.col.f32.bf16.bf16.f32 " \
        "{%0,%1,%2,%3}, {%4,%5,%6,%7}, {%8,%9}, {%0,%1,%2,%3};" \
        : "+f"((d)[0]), "+f"((d)[1]), "+f"((d)[2]), "+f"((d)[3]) \
        : "r"((a)[0]), "r"((a)[1]), "r"((a)[2]), "r"((a)[3]), "r"(b0r), "r"(b1r))

// ---------------------------------------------------------------------------
// Tensor-core GEMM (unchanged from R12 — passed, rel_err 6.4e-6)
// ---------------------------------------------------------------------------
template <int K>
__global__ __launch_bounds__(256) void gemm_tc(
    const float* __restrict__ Aext,
    const int*   __restrict__ tokens,
    const float* __restrict__ Bw,
    const float* __restrict__ bias,
    int a_sel, int c_sel)
{
    __shared__ __align__(16) unsigned sAhi[128 * 9];
    __shared__ __align__(16) unsigned sAlo[128 * 9];
    __shared__ __align__(16) unsigned sBhi[128 * 9];
    __shared__ __align__(16) unsigned sBlo[128 * 9];

    float* C = c_sel ? g_X1 : g_X0;
    const int bm = blockIdx.y, br = blockIdx.x;
    const int tid = threadIdx.x, lane = tid & 31, wid = tid >> 5;

    const int ra = tid >> 1;
    const int kc = (tid & 1) * 8;

    const float* arow;
    if (tokens) {
        int gm = bm * 128 + ra;
        int tok = tokens[(gm & (NB - 1)) * LL + (gm >> 4)];
        tok = min(max(tok, 0), VV - 1);
        arow = Aext + (size_t)tok * K + kc;
    } else {
        const float* A = a_sel ? g_H0 : Aext;
        arow = A + (size_t)(bm * 128 + ra) * K + kc;
    }
    const float* brow = Bw + (size_t)(br * 128 + ra) * K + kc;

    const int wm = (wid & 3) * 32;
    const int wn = (wid >> 2) * 64;
    const int gid = lane >> 2, qc = lane & 3;

    float acc[2][8][4];
#pragma unroll
    for (int mi = 0; mi < 2; mi++)
#pragma unroll
        for (int j = 0; j < 8; j++)
#pragma unroll
            for (int e = 0; e < 4; e++) acc[mi][j][e] = 0.0f;

#define STCVT(dsthi, dstlo, v0, v1)  do {                                   \
        unsigned h_, l_;                                                    \
        cvt_pair((v0).x, (v0).y, h_, l_); dsthi[ra*9 + kc/2 + 0] = h_; dstlo[ra*9 + kc/2 + 0] = l_; \
        cvt_pair((v0).z, (v0).w, h_, l_); dsthi[ra*9 + kc/2 + 1] = h_; dstlo[ra*9 + kc/2 + 1] = l_; \
        cvt_pair((v1).x, (v1).y, h_, l_); dsthi[ra*9 + kc/2 + 2] = h_; dstlo[ra*9 + kc/2 + 2] = l_; \
        cvt_pair((v1).z, (v1).w, h_, l_); dsthi[ra*9 + kc/2 + 3] = h_; dstlo[ra*9 + kc/2 + 3] = l_; \
    } while (0)

    {
        float4 av0 = *(const float4*)(arow);
        float4 av1 = *(const float4*)(arow + 4);
        float4 bv0 = *(const float4*)(brow);
        float4 bv1 = *(const float4*)(brow + 4);
        STCVT(sAhi, sAlo, av0, av1);
        STCVT(sBhi, sBlo, bv0, bv1);
    }
    __syncthreads();

#pragma unroll 1
    for (int k0 = 0; k0 < K; k0 += 16) {
        const bool more = (k0 + 16) < K;
        float4 nav0, nav1, nbv0, nbv1;
        if (more) {
            nav0 = *(const float4*)(arow + k0 + 16);
            nav1 = *(const float4*)(arow + k0 + 20);
            nbv0 = *(const float4*)(brow + k0 + 16);
            nbv1 = *(const float4*)(brow + k0 + 20);
        }

        unsigned ahi[2][4], alo[2][4];
#pragma unroll
        for (int mi = 0; mi < 2; mi++) {
            int r0 = (wm + mi * 16 + gid) * 9;
            int r8 = r0 + 8 * 9;
            ahi[mi][0] = sAhi[r0 + qc];     ahi[mi][1] = sAhi[r8 + qc];
            ahi[mi][2] = sAhi[r0 + qc + 4]; ahi[mi][3] = sAhi[r8 + qc + 4];
            alo[mi][0] = sAlo[r0 + qc];     alo[mi][1] = sAlo[r8 + qc];
            alo[mi][2] = sAlo[r0 + qc + 4]; alo[mi][3] = sAlo[r8 + qc + 4];
        }

#pragma unroll
        for (int j = 0; j < 8; j++) {
            int rb = (wn + j * 8 + gid) * 9;
            unsigned bh0 = sBhi[rb + qc], bh1 = sBhi[rb + qc + 4];
            unsigned bl0 = sBlo[rb + qc], bl1 = sBlo[rb + qc + 4];
#pragma unroll
            for (int mi = 0; mi < 2; mi++) {
                MMA4(acc[mi][j], ahi[mi], bh0, bh1);
                MMA4(acc[mi][j], ahi[mi], bl0, bl1);
                MMA4(acc[mi][j], alo[mi], bh0, bh1);
            }
        }

        if (more) {
            __syncthreads();
            STCVT(sAhi, sAlo, nav0, nav1);
            STCVT(sBhi, sBlo, nbv0, nbv1);
            __syncthreads();
        }
    }
#undef STCVT

#pragma unroll
    for (int j = 0; j < 8; j++) {
        int gc = br * 128 + wn + j * 8 + qc * 2;
        float b0v = bias[gc], b1v = bias[gc + 1];
#pragma unroll
        for (int mi = 0; mi < 2; mi++) {
            int gm0 = bm * 128 + wm + mi * 16 + gid;
            float2 o0 = make_float2(acc[mi][j][0] + b0v, acc[mi][j][1] + b1v);
            float2 o1 = make_float2(acc[mi][j][2] + b0v, acc[mi][j][3] + b1v);
            *(float2*)(C + (size_t)gm0 * G4 + gc)       = o0;
            *(float2*)(C + (size_t)(gm0 + 8) * G4 + gc) = o1;
        }
    }
}

// ---------------------------------------------------------------------------
// Persistent TENSOR-CORE LSTM recurrence. 128 CTAs x 256 thr.
// Per CTA-step: gates[32 m=(g*8+jw)][16 b] = W[32][1024] x h[1024][16].
// Warp w: m-tile mt=w&1, k-quarter kr=w>>1 (16 k-tiles of 16) -> 96 MMAs.
// Smem rows padded to 516 u32 (stride = 4 banks: frag LDS conflict-free).
// h flows between steps as bf16 hi/lo in g_hT (double-buffered, L2 via .cg).
// ---------------------------------------------------------------------------
__global__ __launch_bounds__(256) void lstm_rec(
    const float* __restrict__ Whh,
    float* __restrict__ Out,
    int xsel, int mode)
{
    extern __shared__ __align__(16) unsigned smu[];
    unsigned* sWhi = smu;                  // 32 rows x 516
    unsigned* sWlo = sWhi + 32 * 516;
    unsigned* sHhi = sWlo + 32 * 516;      // 16 rows x 516
    unsigned* sHlo = sHhi + 16 * 516;
    float* red = (float*)(sHlo + 16 * 516);  // 8 warps x 256
    float* gs  = red + 2048;               // 512
    float* xs  = gs + 512;                 // 512

    const float* Xg = xsel ? g_X1 : g_X0;
    const int tid = threadIdx.x, lane = tid & 31, wp = tid >> 5;
    const int gid = lane >> 2, qc = lane & 3;
    const int mt = wp & 1, kr = wp >> 1;

    // ---- preload + convert weight slice: rows m=g*8+jw, k 0..1023 ----
    for (int i = tid; i < 8192; i += 256) {
        int m = i >> 8, cc = i & 255;   // cc = float4 chunk in row
        const float4 wv = *(const float4*)(
            Whh + (size_t)((m >> 3) * HH + blockIdx.x * 8 + (m & 7)) * HH + cc * 4);
        unsigned h0, l0, h1, l1;
        cvt_pair(wv.x, wv.y, h0, l0);
        cvt_pair(wv.z, wv.w, h1, l1);
        int base = m * 516 + cc * 2;
        sWhi[base] = h0; sWhi[base + 1] = h1;
        sWlo[base] = l0; sWlo[base + 1] = l1;
    }
    // zero h rows (t=0 state); sHhi and sHlo are contiguous
    for (int i = tid; i < 2 * 16 * 516; i += 256) sHhi[i] = 0u;

    float creg = 0.0f;
    __syncthreads();

    for (int t = 0; t < LL; t++) {
        // X gate-slice prefetch (overlaps h staging)
        float2 xv;
        int xb = tid >> 4, xr = tid & 15, xg = xr >> 2, xj2 = (xr & 3) << 1;
        xv = *(const float2*)(Xg + (size_t)(t * NB + xb) * G4 + xg * HH + blockIdx.x * 8 + xj2);

        if (t > 0) {
            // stage h_t rows [b][k] (bf16) from L2 into padded smem
            int b = tid >> 4, c = tid & 15;
            const float4* ph = (const float4*)(g_hT_hi[t & 1]) + b * 128 + c * 8;
            const float4* pl = (const float4*)(g_hT_lo[t & 1]) + b * 128 + c * 8;
            float4* dh = (float4*)(sHhi + b * 516 + c * 32);
            float4* dl = (float4*)(sHlo + b * 516 + c * 32);
#pragma unroll
            for (int q = 0; q < 8; q++) dh[q] = __ldcg(ph + q);
#pragma unroll
            for (int q = 0; q < 8; q++) dl[q] = __ldcg(pl + q);
        }
        xs[xj2 * 64 + xg * 16 + xb]       = xv.x;
        xs[(xj2 + 1) * 64 + xg * 16 + xb] = xv.y;
        __syncthreads();

        // ---- tensor-core GEMV: warp (mt, kr), 16 k-tiles, 2 n-tiles ----
        float acc0[4] = {0.f, 0.f, 0.f, 0.f};
        float acc1[4] = {0.f, 0.f, 0.f, 0.f};
        {
            const int aRow0 = (mt * 16 + gid) * 516;
            const int aRow8 = aRow0 + 8 * 516;
            const int bRow0 = gid * 516;
            const int bRow1 = (8 + gid) * 516;
#pragma unroll
            for (int kt = 0; kt < 16; kt++) {
                const int kp = kr * 128 + kt * 8;
                unsigned ah[4], al[4];
                ah[0] = sWhi[aRow0 + kp + qc];
                ah[1] = sWhi[aRow8 + kp + qc];
                ah[2] = sWhi[aRow0 + kp + qc + 4];
                ah[3] = sWhi[aRow8 + kp + qc + 4];
                al[0] = sWlo[aRow0 + kp + qc];
                al[1] = sWlo[aRow8 + kp + qc];
                al[2] = sWlo[aRow0 + kp + qc + 4];
                al[3] = sWlo[aRow8 + kp + qc + 4];
                unsigned bh0 = sHhi[bRow0 + kp + qc], bh1 = sHhi[bRow0 + kp + qc + 4];
                unsigned bl0 = sHlo[bRow0 + kp + qc], bl1 = sHlo[bRow0 + kp + qc + 4];
                MMA4(acc0, ah, bh0, bh1);
                MMA4(acc0, ah, bl0, bl1);
                MMA4(acc0, al, bh0, bh1);
                bh0 = sHhi[bRow1 + kp + qc]; bh1 = sHhi[bRow1 + kp + qc + 4];
                bl0 = sHlo[bRow1 + kp + qc]; bl1 = sHlo[bRow1 + kp + qc + 4];
                MMA4(acc1, ah, bh0, bh1);
                MMA4(acc1, ah, bl0, bl1);
                MMA4(acc1, al, bh0, bh1);
            }
        }
        // write k-partial accumulators
        {
            float4* rw = (float4*)(red + wp * 256 + lane * 8);
            rw[0] = make_float4(acc0[0], acc0[1], acc0[2], acc0[3]);
            rw[1] = make_float4(acc1[0], acc1[1], acc1[2], acc1[3]);
        }
        __syncthreads();

        // ---- k-reduction (warps 0,1) + scatter gates to gs[jw][g][b] ----
        if (wp < 2) {
#pragma unroll
            for (int e = 0; e < 8; e++) {
                float s = red[(0 + wp) * 256 + lane * 8 + e]
                        + red[(2 + wp) * 256 + lane * 8 + e]
                        + red[(4 + wp) * 256 + lane * 8 + e]
                        + red[(6 + wp) * 256 + lane * 8 + e];
                int nt = e >> 2, ee = e & 3;
                int row = wp * 16 + gid + ((ee >> 1) ? 8 : 0);   // m = g*8+jw
                int b = nt * 8 + qc * 2 + (ee & 1);
                gs[(row & 7) * 64 + (row >> 3) * 16 + b] = s;
            }
        }
        __syncthreads();

        // ---- gate nonlinearity + state update (warp wp owns column jw=wp) --
        if (lane < 16) {
            const int b = lane;
            const int j = blockIdx.x * 8 + wp;
            float gi = gs[wp * 64 +  0 + b] + xs[wp * 64 +  0 + b];
            float gf = gs[wp * 64 + 16 + b] + xs[wp * 64 + 16 + b];
            float gg = gs[wp * 64 + 32 + b] + xs[wp * 64 + 32 + b];
            float go = gs[wp * 64 + 48 + b] + xs[wp * 64 + 48 + b];
            float c = sigf(gf) * creg + sigf(gi) * tanhf(gg);
            float h = sigf(go) * tanhf(c);
            creg = c;
            __nv_bfloat16 hh = __float2bfloat16(h);
            __nv_bfloat16 hl = __float2bfloat16(h - __bfloat162float(hh));
            stcg_b16(&g_hT_hi[(t + 1) & 1][b * HH + j], hh);
            stcg_b16(&g_hT_lo[(t + 1) & 1][b * HH + j], hl);
            if (mode == 0)
                g_H0[(size_t)(t * NB + b) * HH + j] = h;
            else
                Out[(size_t)b * (LL * HH) + (size_t)t * HH + j] = h;
        }

        if (t != LL - 1) grid_sync();
    }
}

// ---------------------------------------------------------------------------
extern "C" void kernel_launch(void* const* d_in, const int* in_sizes, int n_in,
                              void* d_out, int out_size)
{
    const int*   x    = nullptr;
    const float* emb  = nullptr;
    const float* wih0 = nullptr;
    const float* bias_[2] = {nullptr, nullptr};
    const float* w4[3] = {nullptr, nullptr, nullptr};
    int nbias = 0, nw = 0;
    for (int i = 0; i < n_in; i++) {
        long long sz = in_sizes[i];
        if (sz == (long long)NB * LL)             x = (const int*)d_in[i];
        else if (sz == (long long)VV * EE)        emb = (const float*)d_in[i];
        else if (sz == (long long)G4 * EE)        wih0 = (const float*)d_in[i];
        else if (sz == (long long)G4)             { if (nbias < 2) bias_[nbias++] = (const float*)d_in[i]; }
        else if (sz == (long long)G4 * HH)        { if (nw < 3) w4[nw++] = (const float*)d_in[i]; }
    }
    if (!x || !emb || !wih0 || nbias < 2 || nw < 3) {
        x = (const int*)d_in[0];
        emb = (const float*)d_in[1];
        wih0 = (const float*)d_in[2];
        w4[0] = (const float*)d_in[3];
        bias_[0] = (const float*)d_in[4];
        w4[1] = (const float*)d_in[5];
        w4[2] = (const float*)d_in[6];
        bias_[1] = (const float*)d_in[7];
    }
    const float* whh0 = w4[0];
    const float* b0   = bias_[0];
    const float* wih1 = w4[1];
    const float* whh1 = w4[2];
    const float* b1   = bias_[1];
    float* out = (float*)d_out;

    // smem: (32+32+16+16)*516 u32 + (2048+512+512) floats = 210432 B
    const int smem_rec = (96 * 516) * 4 + (2048 + 512 + 512) * 4;
    cudaFuncSetAttribute(lstm_rec, cudaFuncAttributeMaxDynamicSharedMemorySize, smem_rec);

    dim3 ggrid(G4 / 128, MM / 128);  // (32, 16)

    gemm_tc<EE><<<ggrid, 256>>>(emb, x, wih0, b0, 0, 0);
    lstm_rec<<<RB, 256, smem_rec>>>(whh0, out, 0, 0);
    gemm_tc<HH><<<ggrid, 256>>>(emb, nullptr, wih1, b1, 1, 1);
    lstm_rec<<<RB, 256, smem_rec>>>(whh1, out, 1, 1);
}

// round 15
// speedup vs baseline: 1.3812x; 1.3745x over previous
#include <cuda_runtime.h>
#include <cuda_bf16.h>

// Problem dims  (V, E, H, N, L = 32000, 512, 1024, 16, 128)
#define VV 32000
#define NB 16
#define LL 128
#define EE 512
#define HH 1024
#define G4 4096
#define MM (NB*LL)
#define RB 128           // persistent recurrence CTAs (1/SM, co-resident)

// Scratch
__device__ __align__(16) float g_X0[(size_t)MM * G4];
__device__ __align__(16) float g_X1[(size_t)MM * G4];
__device__ __align__(16) float g_H0[(size_t)MM * HH];
__device__ __align__(16) float g_h[2][NB * HH];         // h double buffer, [k][b]
__device__ unsigned g_bar_arrive = 0;
__device__ unsigned g_bar_gen    = 0;

__device__ __forceinline__ float sigf(float x) { return 1.0f / (1.0f + __expf(-x)); }

// ---- packed f32x2 helpers -------------------------------------------------
typedef unsigned long long ull;

__device__ __forceinline__ ull pack2(float x) {
    ull r; asm("mov.b64 %0, {%1, %1};" : "=l"(r) : "f"(x)); return r;
}
__device__ __forceinline__ void ffma2(ull& d, ull a, ull b) {
    asm("fma.rn.f32x2 %0, %1, %2, %0;" : "+l"(d) : "l"(a), "l"(b));
}
__device__ __forceinline__ ull fadd2(ull a, ull b) {
    ull d; asm("add.rn.f32x2 %0, %1, %2;" : "=l"(d) : "l"(a), "l"(b)); return d;
}
__device__ __forceinline__ void unpack2(ull v, float& lo, float& hi) {
    asm("mov.b64 {%0, %1}, %2;" : "=f"(lo), "=f"(hi) : "l"(v));
}

// ---- grid-wide barrier: single-counter + generation (measured-best) -------
__device__ __forceinline__ void grid_sync() {
    __threadfence();
    __syncthreads();
    if (threadIdx.x == 0) {
        unsigned gen = ((volatile unsigned*)&g_bar_gen)[0];
        unsigned a = atomicAdd(&g_bar_arrive, 1u);
        if (a == RB - 1) {
            g_bar_arrive = 0;
            __threadfence();
            atomicExch(&g_bar_gen, gen + 1u);
        } else {
            while (((volatile unsigned*)&g_bar_gen)[0] == gen) { }
        }
        __threadfence();
    }
    __syncthreads();
}

// ---- bf16 hi/lo split pack ------------------------------------------------
__device__ __forceinline__ void cvt_pair(float x0, float x1, unsigned& hi, unsigned& lo) {
    __nv_bfloat16 h0 = __float2bfloat16(x0);
    __nv_bfloat16 h1 = __float2bfloat16(x1);
    float r0 = x0 - __bfloat162float(h0);
    float r1 = x1 - __bfloat162float(h1);
    __nv_bfloat162 hp = __halves2bfloat162(h0, h1);
    __nv_bfloat162 lp = __halves2bfloat162(__float2bfloat16(r0), __float2bfloat16(r1));
    hi = *(unsigned*)&hp;
    lo = *(unsigned*)&lp;
}

#define MMA4(d, a, b0r, b1r) \
    asm volatile("mma.sync.aligned.m16n8k16.row.col.f32.bf16.bf16.f32 " \
        "{%0,%1,%2,%3}, {%4,%5,%6,%7}, {%8,%9}, {%0,%1,%2,%3};" \
        : "+f"((d)[0]), "+f"((d)[1]), "+f"((d)[2]), "+f"((d)[3]) \
        : "r"((a)[0]), "r"((a)[1]), "r"((a)[2]), "r"((a)[3]), "r"(b0r), "r"(b1r))

// ---------------------------------------------------------------------------
// Tensor-core GEMM (R12 version — passed, rel_err 6.4e-6)
// ---------------------------------------------------------------------------
template <int K>
__global__ __launch_bounds__(256) void gemm_tc(
    const float* __restrict__ Aext,
    const int*   __restrict__ tokens,
    const float* __restrict__ Bw,
    const float* __restrict__ bias,
    int a_sel, int c_sel)
{
    __shared__ __align__(16) unsigned sAhi[128 * 9];
    __shared__ __align__(16) unsigned sAlo[128 * 9];
    __shared__ __align__(16) unsigned sBhi[128 * 9];
    __shared__ __align__(16) unsigned sBlo[128 * 9];

    float* C = c_sel ? g_X1 : g_X0;
    const int bm = blockIdx.y, br = blockIdx.x;
    const int tid = threadIdx.x, lane = tid & 31, wid = tid >> 5;

    const int ra = tid >> 1;
    const int kc = (tid & 1) * 8;

    const float* arow;
    if (tokens) {
        int gm = bm * 128 + ra;
        int tok = tokens[(gm & (NB - 1)) * LL + (gm >> 4)];
        tok = min(max(tok, 0), VV - 1);
        arow = Aext + (size_t)tok * K + kc;
    } else {
        const float* A = a_sel ? g_H0 : Aext;
        arow = A + (size_t)(bm * 128 + ra) * K + kc;
    }
    const float* brow = Bw + (size_t)(br * 128 + ra) * K + kc;

    const int wm = (wid & 3) * 32;
    const int wn = (wid >> 2) * 64;
    const int gid = lane >> 2, qc = lane & 3;

    float acc[2][8][4];
#pragma unroll
    for (int mi = 0; mi < 2; mi++)
#pragma unroll
        for (int j = 0; j < 8; j++)
#pragma unroll
            for (int e = 0; e < 4; e++) acc[mi][j][e] = 0.0f;

#define STCVT(dsthi, dstlo, v0, v1)  do {                                   \
        unsigned h_, l_;                                                    \
        cvt_pair((v0).x, (v0).y, h_, l_); dsthi[ra*9 + kc/2 + 0] = h_; dstlo[ra*9 + kc/2 + 0] = l_; \
        cvt_pair((v0).z, (v0).w, h_, l_); dsthi[ra*9 + kc/2 + 1] = h_; dstlo[ra*9 + kc/2 + 1] = l_; \
        cvt_pair((v1).x, (v1).y, h_, l_); dsthi[ra*9 + kc/2 + 2] = h_; dstlo[ra*9 + kc/2 + 2] = l_; \
        cvt_pair((v1).z, (v1).w, h_, l_); dsthi[ra*9 + kc/2 + 3] = h_; dstlo[ra*9 + kc/2 + 3] = l_; \
    } while (0)

    {
        float4 av0 = *(const float4*)(arow);
        float4 av1 = *(const float4*)(arow + 4);
        float4 bv0 = *(const float4*)(brow);
        float4 bv1 = *(const float4*)(brow + 4);
        STCVT(sAhi, sAlo, av0, av1);
        STCVT(sBhi, sBlo, bv0, bv1);
    }
    __syncthreads();

#pragma unroll 1
    for (int k0 = 0; k0 < K; k0 += 16) {
        const bool more = (k0 + 16) < K;
        float4 nav0, nav1, nbv0, nbv1;
        if (more) {
            nav0 = *(const float4*)(arow + k0 + 16);
            nav1 = *(const float4*)(arow + k0 + 20);
            nbv0 = *(const float4*)(brow + k0 + 16);
            nbv1 = *(const float4*)(brow + k0 + 20);
        }

        unsigned ahi[2][4], alo[2][4];
#pragma unroll
        for (int mi = 0; mi < 2; mi++) {
            int r0 = (wm + mi * 16 + gid) * 9;
            int r8 = r0 + 8 * 9;
            ahi[mi][0] = sAhi[r0 + qc];     ahi[mi][1] = sAhi[r8 + qc];
            ahi[mi][2] = sAhi[r0 + qc + 4]; ahi[mi][3] = sAhi[r8 + qc + 4];
            alo[mi][0] = sAlo[r0 + qc];     alo[mi][1] = sAlo[r8 + qc];
            alo[mi][2] = sAlo[r0 + qc + 4]; alo[mi][3] = sAlo[r8 + qc + 4];
        }

#pragma unroll
        for (int j = 0; j < 8; j++) {
            int rb = (wn + j * 8 + gid) * 9;
            unsigned bh0 = sBhi[rb + qc], bh1 = sBhi[rb + qc + 4];
            unsigned bl0 = sBlo[rb + qc], bl1 = sBlo[rb + qc + 4];
#pragma unroll
            for (int mi = 0; mi < 2; mi++) {
                MMA4(acc[mi][j], ahi[mi], bh0, bh1);
                MMA4(acc[mi][j], ahi[mi], bl0, bl1);
                MMA4(acc[mi][j], alo[mi], bh0, bh1);
            }
        }

        if (more) {
            __syncthreads();
            STCVT(sAhi, sAlo, nav0, nav1);
            STCVT(sBhi, sBlo, nbv0, nbv1);
            __syncthreads();
        }
    }
#undef STCVT

#pragma unroll
    for (int j = 0; j < 8; j++) {
        int gc = br * 128 + wn + j * 8 + qc * 2;
        float b0v = bias[gc], b1v = bias[gc + 1];
#pragma unroll
        for (int mi = 0; mi < 2; mi++) {
            int gm0 = bm * 128 + wm + mi * 16 + gid;
            float2 o0 = make_float2(acc[mi][j][0] + b0v, acc[mi][j][1] + b1v);
            float2 o1 = make_float2(acc[mi][j][2] + b0v, acc[mi][j][3] + b1v);
            *(float2*)(C + (size_t)gm0 * G4 + gc)       = o0;
            *(float2*)(C + (size_t)(gm0 + 8) * G4 + gc) = o1;
        }
    }
}

// ---------------------------------------------------------------------------
// Persistent FFMA2 LSTM recurrence (R9 version — measured best, ~7.9us/step)
// ---------------------------------------------------------------------------
__global__ __launch_bounds__(256) void lstm_rec(
    const float* __restrict__ Whh,
    float* __restrict__ Out,
    int xsel, int mode)
{
    extern __shared__ __align__(16) float sm[];
    float* ws = sm;                    // 32768 floats: ws[w][g][k]
    float* hs = sm + 32768;            // 20480 floats: h padded [k][20]
    float* gs = hs + 20480;            // 512: reduced gates
    float* xs = gs + 512;              // 512: staged X slice

    const float* Xg = xsel ? g_X1 : g_X0;
    const int tid = threadIdx.x, lane = tid & 31, wp = tid >> 5;
    const int j = blockIdx.x * 8 + wp;

    for (int i = tid; i < 8192; i += 256) {
        int wgk = i * 4;
        int w_ = wgk >> 12, g = (wgk >> 10) & 3, k = wgk & 1023;
        ((float4*)ws)[i] = *(const float4*)(Whh + (size_t)(g * HH + blockIdx.x * 8 + w_) * HH + k);
    }
    for (int i = tid; i < 20480; i += 256) hs[i] = 0.0f;

    float creg = 0.0f;
    __syncthreads();

    for (int t = 0; t < LL; t++) {
        float2 xv;
        int xb = tid >> 4, xr = tid & 15, xg = xr >> 2, xj2 = (xr & 3) << 1;
        xv = *(const float2*)(Xg + (size_t)(t * NB + xb) * G4 + xg * HH + blockIdx.x * 8 + xj2);

        if (t > 0) {
            const float4* src = (const float4*)g_h[t & 1];
            for (int i = tid; i < 4096; i += 256) {
                float4 hv = __ldcg(src + i);
                int k = i >> 2, b4 = (i & 3) << 2;
                *(float4*)(hs + k * 20 + b4) = hv;
            }
        }
        xs[xj2 * 64 + xg * 16 + xb]       = xv.x;
        xs[(xj2 + 1) * 64 + xg * 16 + xb] = xv.y;
        __syncthreads();

        ull acc[4][8];
#pragma unroll
        for (int g = 0; g < 4; g++)
#pragma unroll
            for (int p = 0; p < 8; p++) acc[g][p] = 0ull;

        const float* wr = ws + wp * 4096;
#pragma unroll 8
        for (int i = 0; i < 32; i++) {
            int k = i * 32 + lane;
            ull W0 = pack2(wr[k]);
            ull W1 = pack2(wr[1024 + k]);
            ull W2 = pack2(wr[2048 + k]);
            ull W3 = pack2(wr[3072 + k]);
            const ulonglong2* hp = (const ulonglong2*)(hs + k * 20);
            ulonglong2 ha = hp[0], hb = hp[1], hc = hp[2], hd = hp[3];
            ffma2(acc[0][0], W0, ha.x); ffma2(acc[0][1], W0, ha.y);
            ffma2(acc[0][2], W0, hb.x); ffma2(acc[0][3], W0, hb.y);
            ffma2(acc[0][4], W0, hc.x); ffma2(acc[0][5], W0, hc.y);
            ffma2(acc[0][6], W0, hd.x); ffma2(acc[0][7], W0, hd.y);
            ffma2(acc[1][0], W1, ha.x); ffma2(acc[1][1], W1, ha.y);
            ffma2(acc[1][2], W1, hb.x); ffma2(acc[1][3], W1, hb.y);
            ffma2(acc[1][4], W1, hc.x); ffma2(acc[1][5], W1, hc.y);
            ffma2(acc[1][6], W1, hd.x); ffma2(acc[1][7], W1, hd.y);
            ffma2(acc[2][0], W2, ha.x); ffma2(acc[2][1], W2, ha.y);
            ffma2(acc[2][2], W2, hb.x); ffma2(acc[2][3], W2, hb.y);
            ffma2(acc[2][4], W2, hc.x); ffma2(acc[2][5], W2, hc.y);
            ffma2(acc[2][6], W2, hd.x); ffma2(acc[2][7], W2, hd.y);
            ffma2(acc[3][0], W3, ha.x); ffma2(acc[3][1], W3, ha.y);
            ffma2(acc[3][2], W3, hb.x); ffma2(acc[3][3], W3, hb.y);
            ffma2(acc[3][4], W3, hc.x); ffma2(acc[3][5], W3, hc.y);
            ffma2(acc[3][6], W3, hd.x); ffma2(acc[3][7], W3, hd.y);
        }

        ull* v = &acc[0][0];
#pragma unroll
        for (int m = 16; m >= 1; m >>= 1) {
            int half = m;
#pragma unroll
            for (int i = 0; i < 16; i++) {
                if (i < half) {
                    ull send = (lane & m) ? v[i] : v[i + half];
                    ull recv = __shfl_xor_sync(0xffffffffu, send, m);
                    ull keep = (lane & m) ? v[i + half] : v[i];
                    v[i] = fadd2(keep, recv);
                }
            }
        }
        {
            int g = lane >> 3, p = lane & 7;
            float lo, hi;
            unpack2(v[0], lo, hi);
            gs[wp * 64 + g * 16 + 2 * p]     = lo;
            gs[wp * 64 + g * 16 + 2 * p + 1] = hi;
        }
        __syncwarp();

        if (lane < 16) {
            const int b = lane;
            float gi = gs[wp * 64 +  0 + b] + xs[wp * 64 +  0 + b];
            float gf = gs[wp * 64 + 16 + b] + xs[wp * 64 + 16 + b];
            float gg = gs[wp * 64 + 32 + b] + xs[wp * 64 + 32 + b];
            float go = gs[wp * 64 + 48 + b] + xs[wp * 64 + 48 + b];
            float c = sigf(gf) * creg + sigf(gi) * tanhf(gg);
            float h = sigf(go) * tanhf(c);
            creg = c;
            __stcg(&g_h[(t + 1) & 1][j * 16 + b], h);
            if (mode == 0)
                g_H0[(size_t)(t * NB + b) * HH + j] = h;
            else
                Out[(size_t)b * (LL * HH) + (size_t)t * HH + j] = h;
        }

        if (t != LL - 1) grid_sync();
    }
}

// ---------------------------------------------------------------------------
extern "C" void kernel_launch(void* const* d_in, const int* in_sizes, int n_in,
                              void* d_out, int out_size)
{
    const int*   x    = nullptr;
    const float* emb  = nullptr;
    const float* wih0 = nullptr;
    const float* bias_[2] = {nullptr, nullptr};
    const float* w4[3] = {nullptr, nullptr, nullptr};
    int nbias = 0, nw = 0;
    for (int i = 0; i < n_in; i++) {
        long long sz = in_sizes[i];
        if (sz == (long long)NB * LL)             x = (const int*)d_in[i];
        else if (sz == (long long)VV * EE)        emb = (const float*)d_in[i];
        else if (sz == (long long)G4 * EE)        wih0 = (const float*)d_in[i];
        else if (sz == (long long)G4)             { if (nbias < 2) bias_[nbias++] = (const float*)d_in[i]; }
        else if (sz == (long long)G4 * HH)        { if (nw < 3) w4[nw++] = (const float*)d_in[i]; }
    }
    if (!x || !emb || !wih0 || nbias < 2 || nw < 3) {
        x = (const int*)d_in[0];
        emb = (const float*)d_in[1];
        wih0 = (const float*)d_in[2];
        w4[0] = (const float*)d_in[3];
        bias_[0] = (const float*)d_in[4];
        w4[1] = (const float*)d_in[5];
        w4[2] = (const float*)d_in[6];
        bias_[1] = (const float*)d_in[7];
    }
    const float* whh0 = w4[0];
    const float* b0   = bias_[0];
    const float* wih1 = w4[1];
    const float* whh1 = w4[2];
    const float* b1   = bias_[1];
    float* out = (float*)d_out;

    const int smem_rec = (32768 + 20480 + 512 + 512) * (int)sizeof(float);  // 217088 B
    cudaFuncSetAttribute(lstm_rec, cudaFuncAttributeMaxDynamicSharedMemorySize, smem_rec);

    dim3 ggrid(G4 / 128, MM / 128);  // (32, 16)

    gemm_tc<EE><<<ggrid, 256>>>(emb, x, wih0, b0, 0, 0);
    lstm_rec<<<RB, 256, smem_rec>>>(whh0, out, 0, 0);
    gemm_tc<HH><<<ggrid, 256>>>(emb, nullptr, wih1, b1, 1, 1);
    lstm_rec<<<RB, 256, smem_rec>>>(whh1, out, 1, 1);
}